// round 2
// baseline (speedup 1.0000x reference)
#include <cuda_runtime.h>
#include <math.h>
#include <stdint.h>

// Problem constants
#define Bn   512
#define Rr   5
#define Nn   64
#define Ff   172
#define Tt   100
#define Ee   272     // F + T
#define Kk   444     // F + EF + T
#define Dhh  136     // E / H
#define OUTF 172
#define CATN 1532    // R*E + F

// Inter-kernel scratch: per-relation attention outputs [B, R, E]
__device__ float g_out[Bn * Rr * Ee];
// 1 => mask buffer is byte-packed (bool/uint8); 0 => int32 0/1 per element
__device__ int g_mask_u8;

// ---------------- shared memory layout (floats) ----------------
#define KIN_LD   452
#define SM_KIN   0
#define SM_WTK   28928
#define SM_WTV   34368
#define SM_KV    0
#define SM_Q     39808   // 272
#define SM_SC    40080   // 128 (scores -> weights)
#define SM_ATTN  40208   // 272 (x buffer early, attn later)
#define SM_MB    40480   // 64 mask flags
#define SM_FLAG  40544
#define SM_TOTAL 40548   // floats -> 162192 bytes

__device__ __forceinline__ float warp_reduce(float v) {
    #pragma unroll
    for (int o = 16; o; o >>= 1) v += __shfl_down_sync(0xffffffffu, v, o);
    return v;
}

// Detect mask dtype: scan the first R*B*N/4 words (safe under either layout).
// Any word value > 1 implies byte-packed bools.
__global__ void detect_mask_kernel(const unsigned int* __restrict__ m)
{
    const int nwords = (Rr * Bn * Nn) / 4;   // 40960
    unsigned int acc = 0;
    for (int i = threadIdx.x; i < nwords; i += blockDim.x)
        acc |= m[i];
    // block OR-reduce via shared
    __shared__ unsigned int red[32];
    unsigned int v = acc;
    #pragma unroll
    for (int o = 16; o; o >>= 1) v |= __shfl_xor_sync(0xffffffffu, v, o);
    if ((threadIdx.x & 31) == 0) red[threadIdx.x >> 5] = v;
    __syncthreads();
    if (threadIdx.x == 0) {
        unsigned int t = 0;
        for (int w = 0; w < (int)(blockDim.x >> 5); ++w) t |= red[w];
        g_mask_u8 = (t > 1u) ? 1 : 0;
    }
}

__global__ __launch_bounds__(256, 1)
void attn_kernel(const float* __restrict__ src_node,
                 const float* __restrict__ src_time,
                 const float* __restrict__ neigh_feat,
                 const float* __restrict__ neigh_time,
                 const float* __restrict__ edge_feat,
                 const void* __restrict__ mask_raw,
                 const float* __restrict__ Wq, const float* __restrict__ Wk,
                 const float* __restrict__ Wv, const float* __restrict__ bq,
                 const float* __restrict__ bk, const float* __restrict__ bv,
                 const float* __restrict__ Wo, const float* __restrict__ bo,
                 float* __restrict__ wavg_out)
{
    extern __shared__ float sm[];
    const int b = blockIdx.x, r = blockIdx.y;
    const int tid = threadIdx.x;
    const int lane = tid & 31, warp = tid >> 5;

    // ---- mask load (dtype-robust) + invalid detection (True = padded) ----
    if (tid < Nn) {
        const int idx = (r * Bn + b) * Nn + tid;
        int mv;
        if (g_mask_u8) mv = ((const unsigned char*)mask_raw)[idx];
        else           mv = ((const int*)mask_raw)[idx];
        sm[SM_MB + tid] = (mv != 0) ? 1.f : 0.f;
    }
    __syncthreads();
    if (tid == 0) {
        float allm = 1.f;
        #pragma unroll
        for (int n = 0; n < Nn; ++n) allm = fminf(allm, sm[SM_MB + n]);
        sm[SM_FLAG] = allm;   // 1 => every neighbor padded => invalid
    }
    __syncthreads();
    if (sm[SM_FLAG] > 0.5f) {
        for (int f = tid; f < Ee; f += 256) g_out[(b * Rr + r) * Ee + f] = 0.f;
        if (wavg_out && tid < Nn) wavg_out[(b * Rr + r) * Nn + tid] = 0.f;
        return;
    }

    // ---- x = concat(src_node[b], src_time[b]) into SM_ATTN (temp) ----
    for (int e = tid; e < Ee; e += 256)
        sm[SM_ATTN + e] = (e < Ff) ? src_node[b * Ff + e]
                                   : src_time[b * Tt + (e - Ff)];
    __syncthreads();

    // ---- q[f] = sum_e x[e] * Wq[r,f,e] + bq[r,f] ----
    {
        const float* Wq_r = Wq + (size_t)r * Ee * Ee;
        for (int f = warp; f < Ee; f += 8) {
            float p = 0.f;
            for (int e = lane; e < Ee; e += 32)
                p += sm[SM_ATTN + e] * Wq_r[f * Ee + e];
            p = warp_reduce(p);
            if (lane == 0) sm[SM_Q + f] = p + bq[r * Ee + f];
        }
    }

    // ---- load kin = concat(neigh_feat, edge_feat, neigh_time) [64 x 444] ----
    {
        const float* nf = neigh_feat + ((size_t)b * Rr + r) * Nn * Ff;
        const float* ef = edge_feat  + ((size_t)b * Rr + r) * Nn * Ff;
        const float* tf = neigh_time + ((size_t)b * Rr + r) * Nn * Tt;
        for (int idx = tid; idx < Nn * KIN_LD; idx += 256) {
            int n = idx / KIN_LD;
            int c = idx - n * KIN_LD;
            float v = 0.f;
            if (c < Ff)            v = nf[n * Ff + c];
            else if (c < 2 * Ff)   v = ef[n * Ff + (c - Ff)];
            else if (c < Kk)       v = tf[n * Tt + (c - 2 * Ff)];
            sm[SM_KIN + idx] = v;
        }
    }

    // ---- fused K & V projection GEMM: [64 x 444] @ [444 x 272]^T ----
    const int tx = tid & 15, ty = tid >> 4;   // n = ty*4+i, f = tx + 16*j
    float acck[4][17], accv[4][17];
    #pragma unroll
    for (int i = 0; i < 4; ++i)
        #pragma unroll
        for (int j = 0; j < 17; ++j) { acck[i][j] = 0.f; accv[i][j] = 0.f; }

    const float* Wk_r = Wk + (size_t)r * Ee * Kk;
    const float* Wv_r = Wv + (size_t)r * Ee * Kk;

    for (int kc = 0; kc < 448; kc += 16) {
        __syncthreads();   // covers kin load on iter 0, tile reuse otherwise
        for (int t = tid; t < Ee * 16; t += 256) {
            int f = t >> 4, c = t & 15;
            int col = kc + c;
            float vk = 0.f, vv = 0.f;
            if (col < Kk) {
                vk = Wk_r[f * Kk + col];
                vv = Wv_r[f * Kk + col];
            }
            sm[SM_WTK + f * 20 + c] = vk;
            sm[SM_WTV + f * 20 + c] = vv;
        }
        __syncthreads();
        #pragma unroll
        for (int kk = 0; kk < 16; kk += 4) {
            float4 a[4];
            #pragma unroll
            for (int i = 0; i < 4; ++i)
                a[i] = *(const float4*)&sm[SM_KIN + (ty * 4 + i) * KIN_LD + kc + kk];
            #pragma unroll
            for (int j = 0; j < 17; ++j) {
                float4 wk4 = *(const float4*)&sm[SM_WTK + (tx + 16 * j) * 20 + kk];
                float4 wv4 = *(const float4*)&sm[SM_WTV + (tx + 16 * j) * 20 + kk];
                #pragma unroll
                for (int i = 0; i < 4; ++i) {
                    acck[i][j] += a[i].x * wk4.x + a[i].y * wk4.y
                                + a[i].z * wk4.z + a[i].w * wk4.w;
                    accv[i][j] += a[i].x * wv4.x + a[i].y * wv4.y
                                + a[i].z * wv4.z + a[i].w * wv4.w;
                }
            }
        }
    }

    // ---- write K (+bias) to SMEM (aliases kin/W-tile region) ----
    __syncthreads();
    #pragma unroll
    for (int j = 0; j < 17; ++j) {
        int f = tx + 16 * j;
        float bkf = bk[r * Ee + f];
        #pragma unroll
        for (int i = 0; i < 4; ++i)
            sm[SM_KV + (ty * 4 + i) * Ee + f] = acck[i][j] + bkf;
    }
    __syncthreads();

    // ---- scores[h,n] = (q_h . k_n_h) * scale, masked ----
    {
        const float scale = rsqrtf((float)Dhh);
        for (int p = warp; p < 128; p += 8) {
            int h = p >> 6, n = p & 63;
            float s = 0.f;
            for (int d = lane; d < Dhh; d += 32)
                s += sm[SM_Q + h * Dhh + d] * sm[SM_KV + n * Ee + h * Dhh + d];
            s = warp_reduce(s);
            if (lane == 0)
                sm[SM_SC + p] = (sm[SM_MB + n] > 0.5f) ? -1e30f : s * scale;
        }
    }
    __syncthreads();

    // ---- softmax per head (warps 0,1) ----
    if (warp < 2) {
        int h = warp;
        float v0 = sm[SM_SC + h * 64 + lane];
        float v1 = sm[SM_SC + h * 64 + 32 + lane];
        float mx = fmaxf(v0, v1);
        #pragma unroll
        for (int o = 16; o; o >>= 1) mx = fmaxf(mx, __shfl_xor_sync(0xffffffffu, mx, o));
        float e0 = __expf(v0 - mx), e1 = __expf(v1 - mx);
        float ssum = e0 + e1;
        #pragma unroll
        for (int o = 16; o; o >>= 1) ssum += __shfl_xor_sync(0xffffffffu, ssum, o);
        float inv = 1.f / ssum;
        sm[SM_SC + h * 64 + lane]      = e0 * inv;
        sm[SM_SC + h * 64 + 32 + lane] = e1 * inv;
    }
    __syncthreads();

    // ---- w_avg output (mean over heads) ----
    if (wavg_out && tid < Nn)
        wavg_out[(b * Rr + r) * Nn + tid] =
            0.5f * (sm[SM_SC + tid] + sm[SM_SC + 64 + tid]);

    // ---- write V (+bias) over the K buffer ----
    #pragma unroll
    for (int j = 0; j < 17; ++j) {
        int f = tx + 16 * j;
        float bvf = bv[r * Ee + f];
        #pragma unroll
        for (int i = 0; i < 4; ++i)
            sm[SM_KV + (ty * 4 + i) * Ee + f] = accv[i][j] + bvf;
    }
    __syncthreads();

    // ---- attn[e] = sum_n w[h(e),n] * v[n,e] ----
    for (int e = tid; e < Ee; e += 256) {
        int h = (e >= Dhh) ? 1 : 0;
        float acc = 0.f;
        #pragma unroll 8
        for (int n = 0; n < Nn; ++n)
            acc += sm[SM_SC + h * 64 + n] * sm[SM_KV + n * Ee + e];
        sm[SM_ATTN + e] = acc;
    }
    __syncthreads();

    // ---- output projection: out[f] = sum_e attn[e]*Wo[r,f,e] + bo ----
    {
        const float* Wo_r = Wo + (size_t)r * Ee * Ee;
        for (int f = warp; f < Ee; f += 8) {
            float p = 0.f;
            for (int e = lane; e < Ee; e += 32)
                p += sm[SM_ATTN + e] * Wo_r[f * Ee + e];
            p = warp_reduce(p);
            if (lane == 0) g_out[(b * Rr + r) * Ee + f] = p + bo[r * Ee + f];
        }
    }
}

__global__ __launch_bounds__(256)
void merge_kernel(const float* __restrict__ src_node,
                  const float* __restrict__ W1, const float* __restrict__ b1,
                  const float* __restrict__ W2, const float* __restrict__ b2,
                  float* __restrict__ merged)
{
    __shared__ float cat[CATN];
    __shared__ float hbuf[OUTF];
    const int b = blockIdx.x, tid = threadIdx.x;
    const int lane = tid & 31, warp = tid >> 5;

    for (int j = tid; j < CATN; j += 256)
        cat[j] = (j < Rr * Ee) ? g_out[b * Rr * Ee + j]
                               : src_node[b * Ff + (j - Rr * Ee)];
    __syncthreads();

    for (int f = warp; f < Ff; f += 8) {
        float p = 0.f;
        for (int j = lane; j < CATN; j += 32)
            p += cat[j] * W1[f * CATN + j];
        p = warp_reduce(p);
        if (lane == 0) hbuf[f] = fmaxf(p + b1[f], 0.f);
    }
    __syncthreads();

    for (int o = warp; o < OUTF; o += 8) {
        float p = 0.f;
        for (int e = lane; e < Ff; e += 32)
            p += hbuf[e] * W2[o * Ff + e];
        p = warp_reduce(p);
        if (lane == 0) merged[b * OUTF + o] = p + b2[o];
    }
}

extern "C" void kernel_launch(void* const* d_in, const int* in_sizes, int n_in,
                              void* d_out, int out_size)
{
    const float* src_node = (const float*)d_in[0];
    const float* src_time = (const float*)d_in[1];
    const float* nf       = (const float*)d_in[2];
    const float* nt       = (const float*)d_in[3];
    const float* ef       = (const float*)d_in[4];
    const void*  mask     = d_in[5];
    const float* Wq = (const float*)d_in[6];
    const float* Wk = (const float*)d_in[7];
    const float* Wv = (const float*)d_in[8];
    const float* bq = (const float*)d_in[9];
    const float* bk = (const float*)d_in[10];
    const float* bv = (const float*)d_in[11];
    const float* Wo = (const float*)d_in[12];
    const float* bo = (const float*)d_in[13];
    const float* W1 = (const float*)d_in[14];
    const float* b1 = (const float*)d_in[15];
    const float* W2 = (const float*)d_in[16];
    const float* b2 = (const float*)d_in[17];

    float* merged = (float*)d_out;
    // Output tuple flattened as [merged (B*OUT) | w_avg (B*R*N)]
    float* wavg = nullptr;
    if (out_size >= Bn * OUTF + Bn * Rr * Nn)
        wavg = merged + Bn * OUTF;

    cudaFuncSetAttribute(attn_kernel,
                         cudaFuncAttributeMaxDynamicSharedMemorySize,
                         SM_TOTAL * (int)sizeof(float));

    detect_mask_kernel<<<1, 1024>>>((const unsigned int*)mask);

    dim3 grid(Bn, Rr);
    attn_kernel<<<grid, 256, SM_TOTAL * (int)sizeof(float)>>>(
        src_node, src_time, nf, nt, ef, mask,
        Wq, Wk, Wv, bq, bk, bv, Wo, bo, wavg);

    merge_kernel<<<Bn, 256>>>(src_node, W1, b1, W2, b2, merged);
}

// round 3
// speedup vs baseline: 2.9970x; 2.9970x over previous
#include <cuda_runtime.h>
#include <math.h>
#include <stdint.h>

// Problem constants
#define Bn   512
#define Rr   5
#define Nn   64
#define Ff   172
#define Tt   100
#define Ee   272     // F + T
#define Kk   444     // F + EF + T
#define Dhh  136     // E / H
#define OUTF 172
#define CATN 1532    // R*E + F

// ---------------- inter-kernel scratch ----------------
__device__ float g_X[Bn * Ee];                 // concat(src_node, src_time)
__device__ float g_q[Bn * Rr * Ee];            // q projections
__device__ float g_qk[Bn * Rr * 2 * Kk];       // (q_h · Wk_h) per head
__device__ float g_ctx[Bn * Rr * 2 * Kk];      // softmax-weighted kin per head
__device__ float g_attn[Bn * Rr * Ee];         // ctx · Wv^T + bv
__device__ float g_cat[Bn * CATN];             // [out(b,r*E..) | src_node]
__device__ float g_h1[Bn * OUTF];              // fc1 output
__device__ float g_inv[Bn * Rr];               // 1 => all neighbors padded
__device__ int   g_mask_u8;                    // mask dtype flag

// ==================== mask dtype detection ====================
__global__ void detect_mask_kernel(const unsigned int* __restrict__ m)
{
    const int nwords = (Rr * Bn * Nn) / 4;   // safe under either dtype
    unsigned int acc = 0;
    for (int i = threadIdx.x; i < nwords; i += blockDim.x) acc |= m[i];
    __shared__ unsigned int red[32];
    unsigned int v = acc;
    #pragma unroll
    for (int o = 16; o; o >>= 1) v |= __shfl_xor_sync(0xffffffffu, v, o);
    if ((threadIdx.x & 31) == 0) red[threadIdx.x >> 5] = v;
    __syncthreads();
    if (threadIdx.x == 0) {
        unsigned int t = 0;
        for (int w = 0; w < (int)(blockDim.x >> 5); ++w) t |= red[w];
        g_mask_u8 = (t > 1u) ? 1 : 0;
    }
}

// ==================== prep: X = concat, cat tail = src_node ====================
__global__ void prep_X_kernel(const float* __restrict__ src_node,
                              const float* __restrict__ src_time)
{
    const int b = blockIdx.x, tid = threadIdx.x;
    for (int e = tid; e < Ee; e += 256)
        g_X[b * Ee + e] = (e < Ff) ? src_node[b * Ff + e]
                                   : src_time[b * Tt + (e - Ff)];
    for (int j = tid; j < Ff; j += 256)
        g_cat[b * CATN + Rr * Ee + j] = src_node[b * Ff + j];
}

// ==================== generic batched tiled GEMM ====================
// C[m,n] = sum_k A[m,k] * B(k,n)  (+bias, epilogue)
// BT=true : B row-major [N,K]  (B(k,n) = B[n*ldb+k])   "NT"
// BT=false: B row-major [K,N]  (B(k,n) = B[k*ldb+n])   "NN"
// epi: 0=bias, 1=bias+relu, 2=bias then zero where inv flag set
// M must be a multiple of 64 (always 512 here); N,K arbitrary.
template<bool BT>
__global__ __launch_bounds__(256)
void gemm_kernel(const float* __restrict__ A, int lda, long strideAz,
                 const float* __restrict__ B, int ldb, long strideBz,
                 float* __restrict__ C, int ldc, long strideCz,
                 const float* __restrict__ bias, long strideBiasZ,
                 const float* __restrict__ invf, long strideInvZ, int invRowStride,
                 int N, int K, int epi)
{
    __shared__ float As[16][68];
    __shared__ float Bs[16][68];
    const int z = blockIdx.z;
    A += (size_t)z * strideAz;
    B += (size_t)z * strideBz;
    C += (size_t)z * strideCz;
    const float* bz = bias ? bias + (size_t)z * strideBiasZ : nullptr;
    const int m0 = blockIdx.x * 64, n0 = blockIdx.y * 64;
    const int tid = threadIdx.x;
    const int tn = tid & 15, tm = tid >> 4;

    float acc[4][4];
    #pragma unroll
    for (int i = 0; i < 4; ++i)
        #pragma unroll
        for (int j = 0; j < 4; ++j) acc[i][j] = 0.f;

    for (int k0 = 0; k0 < K; k0 += 16) {
        // A tile -> As[k][m]
        {
            const int kt = tid & 15, mt0 = tid >> 4;
            #pragma unroll
            for (int i = 0; i < 4; ++i) {
                const int mt = mt0 + i * 16;
                const int k = k0 + kt;
                As[kt][mt] = (k < K) ? A[(size_t)(m0 + mt) * lda + k] : 0.f;
            }
        }
        // B tile -> Bs[k][n]
        if (BT) {
            const int kt = tid & 15, nt0 = tid >> 4;
            #pragma unroll
            for (int i = 0; i < 4; ++i) {
                const int nt = nt0 + i * 16;
                const int k = k0 + kt, n = n0 + nt;
                Bs[kt][nt] = (k < K && n < N) ? B[(size_t)n * ldb + k] : 0.f;
            }
        } else {
            const int nt = tid & 63, kt0 = tid >> 6;
            #pragma unroll
            for (int i = 0; i < 4; ++i) {
                const int kt = kt0 + i * 4;
                const int k = k0 + kt, n = n0 + nt;
                Bs[kt][nt] = (k < K && n < N) ? B[(size_t)k * ldb + n] : 0.f;
            }
        }
        __syncthreads();
        #pragma unroll
        for (int kt = 0; kt < 16; ++kt) {
            const float4 a4 = *(const float4*)&As[kt][tm * 4];
            const float4 b4 = *(const float4*)&Bs[kt][tn * 4];
            const float av[4] = {a4.x, a4.y, a4.z, a4.w};
            const float bw[4] = {b4.x, b4.y, b4.z, b4.w};
            #pragma unroll
            for (int i = 0; i < 4; ++i)
                #pragma unroll
                for (int j = 0; j < 4; ++j)
                    acc[i][j] += av[i] * bw[j];
        }
        __syncthreads();
    }

    #pragma unroll
    for (int i = 0; i < 4; ++i) {
        const int row = m0 + tm * 4 + i;
        float vmul = 1.f;
        if (epi == 2 && invf) {
            const float fl = invf[(size_t)z * strideInvZ + (size_t)row * invRowStride];
            vmul = (fl > 0.5f) ? 0.f : 1.f;
        }
        #pragma unroll
        for (int j = 0; j < 4; ++j) {
            const int col = n0 + tn * 4 + j;
            if (col < N) {
                float v = acc[i][j] + (bz ? bz[col] : 0.f);
                if (epi == 1) v = fmaxf(v, 0.f);
                v *= vmul;
                C[(size_t)row * ldc + col] = v;
            }
        }
    }
}

// ==================== streaming attention (memory-bound) ====================
// Per (b,r): load kin [64,444] once, scores = qk . kin_n, softmax, ctx = w . kin
#define KIN_LD  449
#define A_KIN   0                  // 64*449 = 28736
#define A_QK    28736              // 2*444  = 888
#define A_W     29624              // 128 scores->weights
#define A_MB    29752              // 64 mask
#define A_FLAG  29816
#define A_TOT   29817              // floats -> 119268 bytes

__device__ __forceinline__ float warp_reduce(float v) {
    #pragma unroll
    for (int o = 16; o; o >>= 1) v += __shfl_down_sync(0xffffffffu, v, o);
    return v;
}

__global__ __launch_bounds__(256, 1)
void attn_stream_kernel(const float* __restrict__ neigh_feat,
                        const float* __restrict__ neigh_time,
                        const float* __restrict__ edge_feat,
                        const void* __restrict__ mask_raw,
                        float* __restrict__ wavg_out)
{
    extern __shared__ float sm[];
    const int b = blockIdx.x, r = blockIdx.y;
    const int tid = threadIdx.x;
    const int lane = tid & 31, warp = tid >> 5;
    const int idx = b * Rr + r;

    // mask (dtype-robust; True = padded)
    if (tid < Nn) {
        const int mi = (r * Bn + b) * Nn + tid;
        int mv;
        if (g_mask_u8) mv = ((const unsigned char*)mask_raw)[mi];
        else           mv = ((const int*)mask_raw)[mi];
        sm[A_MB + tid] = (mv != 0) ? 1.f : 0.f;
    }
    __syncthreads();
    if (tid == 0) {
        float allm = 1.f;
        #pragma unroll
        for (int n = 0; n < Nn; ++n) allm = fminf(allm, sm[A_MB + n]);
        sm[A_FLAG] = allm;
    }
    __syncthreads();
    if (sm[A_FLAG] > 0.5f) {
        if (tid == 0) g_inv[idx] = 1.f;
        for (int t = tid; t < 2 * Kk; t += 256) g_ctx[(size_t)idx * 2 * Kk + t] = 0.f;
        if (wavg_out && tid < Nn) wavg_out[idx * Nn + tid] = 0.f;
        return;
    }
    if (tid == 0) g_inv[idx] = 0.f;

    // load qk vectors (2 x 444)
    for (int t = tid; t < 2 * Kk; t += 256)
        sm[A_QK + t] = g_qk[(size_t)idx * 2 * Kk + t];

    // load kin = concat(neigh_feat, edge_feat, neigh_time) [64 x 444]
    {
        const float* nf = neigh_feat + (size_t)idx * Nn * Ff;
        const float* ef = edge_feat  + (size_t)idx * Nn * Ff;
        const float* tf = neigh_time + (size_t)idx * Nn * Tt;
        for (int t = tid; t < Nn * Kk; t += 256) {
            const int n = t / Kk;
            const int c = t - n * Kk;
            float v;
            if (c < Ff)            v = nf[n * Ff + c];
            else if (c < 2 * Ff)   v = ef[n * Ff + (c - Ff)];
            else                   v = tf[n * Tt + (c - 2 * Ff)];
            sm[A_KIN + n * KIN_LD + c] = v;
        }
    }
    __syncthreads();

    // scores[h,n] = scale * (qk[h,:] . kin[n,:]), masked
    {
        const float scale = rsqrtf((float)Dhh);
        for (int n = warp; n < Nn; n += 8) {
            float a0 = 0.f, a1 = 0.f;
            for (int c = lane; c < Kk; c += 32) {
                const float kv = sm[A_KIN + n * KIN_LD + c];
                a0 += sm[A_QK + c] * kv;
                a1 += sm[A_QK + Kk + c] * kv;
            }
            a0 = warp_reduce(a0);
            a1 = warp_reduce(a1);
            if (lane == 0) {
                const bool pad = sm[A_MB + n] > 0.5f;
                sm[A_W + n]      = pad ? -1e30f : a0 * scale;
                sm[A_W + 64 + n] = pad ? -1e30f : a1 * scale;
            }
        }
    }
    __syncthreads();

    // softmax per head
    if (warp < 2) {
        const int h = warp;
        float v0 = sm[A_W + h * 64 + lane];
        float v1 = sm[A_W + h * 64 + 32 + lane];
        float mx = fmaxf(v0, v1);
        #pragma unroll
        for (int o = 16; o; o >>= 1) mx = fmaxf(mx, __shfl_xor_sync(0xffffffffu, mx, o));
        const float e0 = __expf(v0 - mx), e1 = __expf(v1 - mx);
        float ss = e0 + e1;
        #pragma unroll
        for (int o = 16; o; o >>= 1) ss += __shfl_xor_sync(0xffffffffu, ss, o);
        const float inv = 1.f / ss;
        sm[A_W + h * 64 + lane]      = e0 * inv;
        sm[A_W + h * 64 + 32 + lane] = e1 * inv;
    }
    __syncthreads();

    // w_avg output
    if (wavg_out && tid < Nn)
        wavg_out[idx * Nn + tid] = 0.5f * (sm[A_W + tid] + sm[A_W + 64 + tid]);

    // ctx[h,c] = sum_n w[h,n] * kin[n,c]
    for (int c = tid; c < Kk; c += 256) {
        float a0 = 0.f, a1 = 0.f;
        #pragma unroll 8
        for (int n = 0; n < Nn; ++n) {
            const float kv = sm[A_KIN + n * KIN_LD + c];
            a0 += sm[A_W + n] * kv;
            a1 += sm[A_W + 64 + n] * kv;
        }
        g_ctx[(size_t)idx * 2 * Kk + c]      = a0;
        g_ctx[(size_t)idx * 2 * Kk + Kk + c] = a1;
    }
}

// ==================== launch ====================
extern "C" void kernel_launch(void* const* d_in, const int* in_sizes, int n_in,
                              void* d_out, int out_size)
{
    const float* src_node = (const float*)d_in[0];
    const float* src_time = (const float*)d_in[1];
    const float* nf       = (const float*)d_in[2];
    const float* nt       = (const float*)d_in[3];
    const float* ef       = (const float*)d_in[4];
    const void*  mask     = d_in[5];
    const float* Wq = (const float*)d_in[6];
    const float* Wk = (const float*)d_in[7];
    const float* Wv = (const float*)d_in[8];
    const float* bq = (const float*)d_in[9];
    // bk (d_in[10]) dropped: per-row constant shift, softmax-invariant
    const float* bv = (const float*)d_in[11];
    const float* Wo = (const float*)d_in[12];
    const float* bo = (const float*)d_in[13];
    const float* W1 = (const float*)d_in[14];
    const float* b1 = (const float*)d_in[15];
    const float* W2 = (const float*)d_in[16];
    const float* b2 = (const float*)d_in[17];

    float* merged = (float*)d_out;
    float* wavg = nullptr;
    if (out_size >= Bn * OUTF + Bn * Rr * Nn)
        wavg = merged + Bn * OUTF;

    // device-global symbol addresses
    float *pX, *pq, *pqk, *pctx, *pattn, *pcat, *ph1, *pinv;
    cudaGetSymbolAddress((void**)&pX,    g_X);
    cudaGetSymbolAddress((void**)&pq,    g_q);
    cudaGetSymbolAddress((void**)&pqk,   g_qk);
    cudaGetSymbolAddress((void**)&pctx,  g_ctx);
    cudaGetSymbolAddress((void**)&pattn, g_attn);
    cudaGetSymbolAddress((void**)&pcat,  g_cat);
    cudaGetSymbolAddress((void**)&ph1,   g_h1);
    cudaGetSymbolAddress((void**)&pinv,  g_inv);

    cudaFuncSetAttribute(attn_stream_kernel,
                         cudaFuncAttributeMaxDynamicSharedMemorySize,
                         A_TOT * (int)sizeof(float));

    detect_mask_kernel<<<1, 1024>>>((const unsigned int*)mask);
    prep_X_kernel<<<Bn, 256>>>(src_node, src_time);

    // q = X @ Wq[r]^T + bq   (NT, z=r)  M=512,N=272,K=272
    {
        dim3 g(Bn / 64, (Ee + 63) / 64, Rr);
        gemm_kernel<true><<<g, 256>>>(pX, Ee, 0,
                                      Wq, Ee, (long)Ee * Ee,
                                      pq, Rr * Ee, Ee,
                                      bq, Ee,
                                      nullptr, 0, 0,
                                      Ee, Ee, 0);
    }
    // qk = q_h @ Wk_h   (NN, z=2r+h)  M=512,N=444,K=136
    {
        dim3 g(Bn / 64, (Kk + 63) / 64, Rr * 2);
        gemm_kernel<false><<<g, 256>>>(pq, Rr * Ee, Dhh,
                                       Wk, Kk, (long)Dhh * Kk,
                                       pqk, Rr * 2 * Kk, Kk,
                                       nullptr, 0,
                                       nullptr, 0, 0,
                                       Kk, Dhh, 0);
    }
    // streaming attention -> ctx, wavg, inv flags
    {
        dim3 g(Bn, Rr);
        attn_stream_kernel<<<g, 256, A_TOT * (int)sizeof(float)>>>(
            nf, nt, ef, mask, wavg);
    }
    // attn = ctx @ Wv_h^T + bv   (NT, z=2r+h)  M=512,N=136,K=444
    {
        dim3 g(Bn / 64, (Dhh + 63) / 64, Rr * 2);
        gemm_kernel<true><<<g, 256>>>(pctx, Rr * 2 * Kk, Kk,
                                      Wv, Kk, (long)Dhh * Kk,
                                      pattn, Rr * Ee, Dhh,
                                      bv, Dhh,
                                      nullptr, 0, 0,
                                      Dhh, Kk, 0);
    }
    // out = attn @ Wo[r]^T + bo, zeroed where invalid -> g_cat[:, r*E..]
    {
        dim3 g(Bn / 64, (Ee + 63) / 64, Rr);
        gemm_kernel<true><<<g, 256>>>(pattn, Rr * Ee, Ee,
                                      Wo, Ee, (long)Ee * Ee,
                                      pcat, CATN, Ee,
                                      bo, Ee,
                                      pinv, 1, Rr,
                                      Ee, Ee, 2);
    }
    // fc1: h = relu(cat @ W1^T + b1)   M=512,N=172,K=1532
    {
        dim3 g(Bn / 64, (OUTF + 63) / 64, 1);
        gemm_kernel<true><<<g, 256>>>(pcat, CATN, 0,
                                      W1, CATN, 0,
                                      ph1, OUTF, 0,
                                      b1, 0,
                                      nullptr, 0, 0,
                                      OUTF, CATN, 1);
    }
    // fc2: merged = h @ W2^T + b2   M=512,N=172,K=172
    {
        dim3 g(Bn / 64, (OUTF + 63) / 64, 1);
        gemm_kernel<true><<<g, 256>>>(ph1, OUTF, 0,
                                      W2, OUTF, 0,
                                      merged, OUTF, 0,
                                      b2, 0,
                                      nullptr, 0, 0,
                                      OUTF, OUTF, 0);
    }
}

// round 4
// speedup vs baseline: 6.2874x; 2.0979x over previous
#include <cuda_runtime.h>
#include <math.h>
#include <stdint.h>

// Problem constants
#define Bn   512
#define Rr   5
#define Nn   64
#define Ff   172
#define Tt   100
#define Ee   272     // F + T
#define Kk   444     // F + EF + T
#define Dhh  136     // E / H
#define OUTF 172
#define CATN 1532    // R*E + F

// ---------------- inter-kernel scratch ----------------
__device__ float g_X[Bn * Ee];                 // concat(src_node, src_time)
__device__ float g_q[Bn * Rr * Ee];            // q projections
__device__ float g_qk[Bn * Rr * 2 * Kk];       // (q_h · Wk_h) per head
__device__ float g_w[Bn * Rr * 2 * Nn];        // softmax weights per head
__device__ float g_ctx[Bn * Rr * 2 * Kk];      // softmax-weighted kin per head
__device__ float g_attn[Bn * Rr * Ee];         // ctx · Wv^T + bv
__device__ float g_cat[Bn * CATN];             // [out(b,r*E..) | src_node]
__device__ float g_h1[Bn * OUTF];              // fc1 output
__device__ float g_inv[Bn * Rr];               // 1 => all neighbors padded
__device__ int   g_mask_u8;                    // mask dtype flag

__device__ __forceinline__ float warp_reduce(float v) {
    #pragma unroll
    for (int o = 16; o; o >>= 1) v += __shfl_down_sync(0xffffffffu, v, o);
    return v;
}

// ==================== mask dtype detection ====================
// Scan first 8192 words (safe under either dtype); any value > 1 => byte-packed.
__global__ void detect_mask_kernel(const unsigned int* __restrict__ m)
{
    const int nwords = 8192;
    unsigned int acc = 0;
    for (int i = threadIdx.x; i < nwords; i += blockDim.x) acc |= m[i];
    __shared__ unsigned int red[32];
    unsigned int v = acc;
    #pragma unroll
    for (int o = 16; o; o >>= 1) v |= __shfl_xor_sync(0xffffffffu, v, o);
    if ((threadIdx.x & 31) == 0) red[threadIdx.x >> 5] = v;
    __syncthreads();
    if (threadIdx.x == 0) {
        unsigned int t = 0;
        for (int w = 0; w < (int)(blockDim.x >> 5); ++w) t |= red[w];
        g_mask_u8 = (t > 1u) ? 1 : 0;
    }
}

// ==================== prep: X = concat, cat tail = src_node ====================
__global__ void prep_X_kernel(const float* __restrict__ src_node,
                              const float* __restrict__ src_time)
{
    const int b = blockIdx.x, tid = threadIdx.x;
    for (int e = tid; e < Ee; e += 256)
        g_X[b * Ee + e] = (e < Ff) ? src_node[b * Ff + e]
                                   : src_time[b * Tt + (e - Ff)];
    for (int j = tid; j < Ff; j += 256)
        g_cat[b * CATN + Rr * Ee + j] = src_node[b * Ff + j];
}

// ==================== generic batched tiled GEMM ====================
// C[m,n] = sum_k A[m,k] * B(k,n)  (+bias, epilogue)
// BT=true : B row-major [N,K]; BT=false: B row-major [K,N]
// epi: 0=bias, 1=bias+relu, 2=bias then zero where inv flag set
template<bool BT>
__global__ __launch_bounds__(256)
void gemm_kernel(const float* __restrict__ A, int lda, long strideAz,
                 const float* __restrict__ B, int ldb, long strideBz,
                 float* __restrict__ C, int ldc, long strideCz,
                 const float* __restrict__ bias, long strideBiasZ,
                 const float* __restrict__ invf, long strideInvZ, int invRowStride,
                 int N, int K, int epi)
{
    __shared__ float As[16][68];
    __shared__ float Bs[16][68];
    const int z = blockIdx.z;
    A += (size_t)z * strideAz;
    B += (size_t)z * strideBz;
    C += (size_t)z * strideCz;
    const float* bz = bias ? bias + (size_t)z * strideBiasZ : nullptr;
    const int m0 = blockIdx.x * 64, n0 = blockIdx.y * 64;
    const int tid = threadIdx.x;
    const int tn = tid & 15, tm = tid >> 4;

    float acc[4][4];
    #pragma unroll
    for (int i = 0; i < 4; ++i)
        #pragma unroll
        for (int j = 0; j < 4; ++j) acc[i][j] = 0.f;

    for (int k0 = 0; k0 < K; k0 += 16) {
        {
            const int kt = tid & 15, mt0 = tid >> 4;
            #pragma unroll
            for (int i = 0; i < 4; ++i) {
                const int mt = mt0 + i * 16;
                const int k = k0 + kt;
                As[kt][mt] = (k < K) ? A[(size_t)(m0 + mt) * lda + k] : 0.f;
            }
        }
        if (BT) {
            const int kt = tid & 15, nt0 = tid >> 4;
            #pragma unroll
            for (int i = 0; i < 4; ++i) {
                const int nt = nt0 + i * 16;
                const int k = k0 + kt, n = n0 + nt;
                Bs[kt][nt] = (k < K && n < N) ? B[(size_t)n * ldb + k] : 0.f;
            }
        } else {
            const int nt = tid & 63, kt0 = tid >> 6;
            #pragma unroll
            for (int i = 0; i < 4; ++i) {
                const int kt = kt0 + i * 4;
                const int k = k0 + kt, n = n0 + nt;
                Bs[kt][nt] = (k < K && n < N) ? B[(size_t)k * ldb + n] : 0.f;
            }
        }
        __syncthreads();
        #pragma unroll
        for (int kt = 0; kt < 16; ++kt) {
            const float4 a4 = *(const float4*)&As[kt][tm * 4];
            const float4 b4 = *(const float4*)&Bs[kt][tn * 4];
            const float av[4] = {a4.x, a4.y, a4.z, a4.w};
            const float bw[4] = {b4.x, b4.y, b4.z, b4.w};
            #pragma unroll
            for (int i = 0; i < 4; ++i)
                #pragma unroll
                for (int j = 0; j < 4; ++j)
                    acc[i][j] += av[i] * bw[j];
        }
        __syncthreads();
    }

    #pragma unroll
    for (int i = 0; i < 4; ++i) {
        const int row = m0 + tm * 4 + i;
        float vmul = 1.f;
        if (epi == 2 && invf) {
            const float fl = invf[(size_t)z * strideInvZ + (size_t)row * invRowStride];
            vmul = (fl > 0.5f) ? 0.f : 1.f;
        }
        #pragma unroll
        for (int j = 0; j < 4; ++j) {
            const int col = n0 + tn * 4 + j;
            if (col < N) {
                float v = acc[i][j] + (bz ? bz[col] : 0.f);
                if (epi == 1) v = fmaxf(v, 0.f);
                v *= vmul;
                C[(size_t)row * ldc + col] = v;
            }
        }
    }
}

// ==================== pass A: scores + softmax (smem-light) ====================
__global__ __launch_bounds__(256)
void score_kernel(const float* __restrict__ neigh_feat,
                  const float* __restrict__ neigh_time,
                  const float* __restrict__ edge_feat,
                  const void* __restrict__ mask_raw,
                  float* __restrict__ wavg_out)
{
    __shared__ float qks[2 * Kk];
    __shared__ float wsm[128];
    __shared__ float mb[Nn];
    __shared__ float flag;
    const int b = blockIdx.x, r = blockIdx.y;
    const int tid = threadIdx.x;
    const int lane = tid & 31, warp = tid >> 5;
    const int idx = b * Rr + r;

    if (tid < Nn) {
        const int mi = (r * Bn + b) * Nn + tid;
        int mv;
        if (g_mask_u8) mv = ((const unsigned char*)mask_raw)[mi];
        else           mv = ((const int*)mask_raw)[mi];
        mb[tid] = (mv != 0) ? 1.f : 0.f;
    }
    __syncthreads();
    if (tid == 0) {
        float allm = 1.f;
        #pragma unroll
        for (int n = 0; n < Nn; ++n) allm = fminf(allm, mb[n]);
        flag = allm;
        g_inv[idx] = allm;
    }
    __syncthreads();
    if (flag > 0.5f) {
        // all padded: zero weights => zero ctx downstream; zero w_avg
        if (tid < 128) g_w[(size_t)idx * 128 + tid] = 0.f;
        if (wavg_out && tid < Nn) wavg_out[idx * Nn + tid] = 0.f;
        return;
    }

    for (int t = tid; t < 2 * Kk; t += 256)
        qks[t] = g_qk[(size_t)idx * 2 * Kk + t];
    __syncthreads();

    const float scale = rsqrtf((float)Dhh);
    for (int n = warp; n < Nn; n += 8) {
        const float* pn = neigh_feat + ((size_t)idx * Nn + n) * Ff;
        const float* pe = edge_feat  + ((size_t)idx * Nn + n) * Ff;
        const float* pt = neigh_time + ((size_t)idx * Nn + n) * Tt;
        float a0 = 0.f, a1 = 0.f;
        for (int c = lane; c < Ff; c += 32) {
            const float v = pn[c];
            a0 += qks[c] * v;
            a1 += qks[Kk + c] * v;
        }
        for (int c = lane; c < Ff; c += 32) {
            const float v = pe[c];
            a0 += qks[Ff + c] * v;
            a1 += qks[Kk + Ff + c] * v;
        }
        for (int c = lane; c < Tt; c += 32) {
            const float v = pt[c];
            a0 += qks[2 * Ff + c] * v;
            a1 += qks[Kk + 2 * Ff + c] * v;
        }
        a0 = warp_reduce(a0);
        a1 = warp_reduce(a1);
        if (lane == 0) {
            const bool pad = mb[n] > 0.5f;
            wsm[n]      = pad ? -1e30f : a0 * scale;
            wsm[64 + n] = pad ? -1e30f : a1 * scale;
        }
    }
    __syncthreads();

    if (warp < 2) {
        const int h = warp;
        float v0 = wsm[h * 64 + lane];
        float v1 = wsm[h * 64 + 32 + lane];
        float mx = fmaxf(v0, v1);
        #pragma unroll
        for (int o = 16; o; o >>= 1) mx = fmaxf(mx, __shfl_xor_sync(0xffffffffu, mx, o));
        const float e0 = __expf(v0 - mx), e1 = __expf(v1 - mx);
        float ss = e0 + e1;
        #pragma unroll
        for (int o = 16; o; o >>= 1) ss += __shfl_xor_sync(0xffffffffu, ss, o);
        const float inv = 1.f / ss;
        wsm[h * 64 + lane]      = e0 * inv;
        wsm[h * 64 + 32 + lane] = e1 * inv;
    }
    __syncthreads();

    if (tid < 128) g_w[(size_t)idx * 128 + tid] = wsm[tid];
    if (wavg_out && tid < Nn)
        wavg_out[idx * Nn + tid] = 0.5f * (wsm[tid] + wsm[64 + tid]);
}

// ==================== pass B: ctx = w . kin (L2-resident) ====================
__global__ __launch_bounds__(256)
void ctx_kernel(const float* __restrict__ neigh_feat,
                const float* __restrict__ neigh_time,
                const float* __restrict__ edge_feat)
{
    __shared__ float wsm[128];
    const int b = blockIdx.x, r = blockIdx.y;
    const int tid = threadIdx.x;
    const int idx = b * Rr + r;

    if (tid < 128) wsm[tid] = g_w[(size_t)idx * 128 + tid];
    __syncthreads();

    for (int c = tid; c < Kk; c += 256) {
        const float* p;
        int stride;
        if (c < Ff)            { p = neigh_feat + (size_t)idx * Nn * Ff + c;            stride = Ff; }
        else if (c < 2 * Ff)   { p = edge_feat  + (size_t)idx * Nn * Ff + (c - Ff);     stride = Ff; }
        else                   { p = neigh_time + (size_t)idx * Nn * Tt + (c - 2 * Ff); stride = Tt; }
        float a0 = 0.f, a1 = 0.f;
        #pragma unroll 8
        for (int n = 0; n < Nn; ++n) {
            const float v = p[(size_t)n * stride];
            a0 += wsm[n] * v;
            a1 += wsm[64 + n] * v;
        }
        g_ctx[(size_t)idx * 2 * Kk + c]      = a0;
        g_ctx[(size_t)idx * 2 * Kk + Kk + c] = a1;
    }
}

// ==================== launch ====================
extern "C" void kernel_launch(void* const* d_in, const int* in_sizes, int n_in,
                              void* d_out, int out_size)
{
    const float* src_node = (const float*)d_in[0];
    const float* src_time = (const float*)d_in[1];
    const float* nf       = (const float*)d_in[2];
    const float* nt       = (const float*)d_in[3];
    const float* ef       = (const float*)d_in[4];
    const void*  mask     = d_in[5];
    const float* Wq = (const float*)d_in[6];
    const float* Wk = (const float*)d_in[7];
    const float* Wv = (const float*)d_in[8];
    const float* bq = (const float*)d_in[9];
    // bk (d_in[10]) dropped: per-row constant shift, softmax-invariant
    const float* bv = (const float*)d_in[11];
    const float* Wo = (const float*)d_in[12];
    const float* bo = (const float*)d_in[13];
    const float* W1 = (const float*)d_in[14];
    const float* b1 = (const float*)d_in[15];
    const float* W2 = (const float*)d_in[16];
    const float* b2 = (const float*)d_in[17];

    float* merged = (float*)d_out;
    float* wavg = nullptr;
    if (out_size >= Bn * OUTF + Bn * Rr * Nn)
        wavg = merged + Bn * OUTF;

    float *pX, *pq, *pqk, *pctx, *pattn, *pcat, *ph1, *pinv;
    cudaGetSymbolAddress((void**)&pX,    g_X);
    cudaGetSymbolAddress((void**)&pq,    g_q);
    cudaGetSymbolAddress((void**)&pqk,   g_qk);
    cudaGetSymbolAddress((void**)&pctx,  g_ctx);
    cudaGetSymbolAddress((void**)&pattn, g_attn);
    cudaGetSymbolAddress((void**)&pcat,  g_cat);
    cudaGetSymbolAddress((void**)&ph1,   g_h1);
    cudaGetSymbolAddress((void**)&pinv,  g_inv);

    detect_mask_kernel<<<1, 1024>>>((const unsigned int*)mask);
    prep_X_kernel<<<Bn, 256>>>(src_node, src_time);

    // q = X @ Wq[r]^T + bq   (NT, z=r)  M=512,N=272,K=272
    {
        dim3 g(Bn / 64, (Ee + 63) / 64, Rr);
        gemm_kernel<true><<<g, 256>>>(pX, Ee, 0,
                                      Wq, Ee, (long)Ee * Ee,
                                      pq, Rr * Ee, Ee,
                                      bq, Ee,
                                      nullptr, 0, 0,
                                      Ee, Ee, 0);
    }
    // qk = q_h @ Wk_h   (NN, z=2r+h)  M=512,N=444,K=136
    {
        dim3 g(Bn / 64, (Kk + 63) / 64, Rr * 2);
        gemm_kernel<false><<<g, 256>>>(pq, Rr * Ee, Dhh,
                                       Wk, Kk, (long)Dhh * Kk,
                                       pqk, Rr * 2 * Kk, Kk,
                                       nullptr, 0,
                                       nullptr, 0, 0,
                                       Kk, Dhh, 0);
    }
    // pass A: scores + softmax -> g_w, wavg, g_inv
    {
        dim3 g(Bn, Rr);
        score_kernel<<<g, 256>>>(nf, nt, ef, mask, wavg);
    }
    // pass B: ctx = w . kin
    {
        dim3 g(Bn, Rr);
        ctx_kernel<<<g, 256>>>(nf, nt, ef);
    }
    // attn = ctx @ Wv_h^T + bv   (NT, z=2r+h)  M=512,N=136,K=444
    {
        dim3 g(Bn / 64, (Dhh + 63) / 64, Rr * 2);
        gemm_kernel<true><<<g, 256>>>(pctx, Rr * 2 * Kk, Kk,
                                      Wv, Kk, (long)Dhh * Kk,
                                      pattn, Rr * Ee, Dhh,
                                      bv, Dhh,
                                      nullptr, 0, 0,
                                      Dhh, Kk, 0);
    }
    // out = attn @ Wo[r]^T + bo, zeroed where invalid -> g_cat[:, r*E..]
    {
        dim3 g(Bn / 64, (Ee + 63) / 64, Rr);
        gemm_kernel<true><<<g, 256>>>(pattn, Rr * Ee, Ee,
                                      Wo, Ee, (long)Ee * Ee,
                                      pcat, CATN, Ee,
                                      bo, Ee,
                                      pinv, 1, Rr,
                                      Ee, Ee, 2);
    }
    // fc1: h = relu(cat @ W1^T + b1)
    {
        dim3 g(Bn / 64, (OUTF + 63) / 64, 1);
        gemm_kernel<true><<<g, 256>>>(pcat, CATN, 0,
                                      W1, CATN, 0,
                                      ph1, OUTF, 0,
                                      b1, 0,
                                      nullptr, 0, 0,
                                      OUTF, CATN, 1);
    }
    // fc2: merged = h @ W2^T + b2
    {
        dim3 g(Bn / 64, (OUTF + 63) / 64, 1);
        gemm_kernel<true><<<g, 256>>>(ph1, OUTF, 0,
                                      W2, OUTF, 0,
                                      merged, OUTF, 0,
                                      b2, 0,
                                      nullptr, 0, 0,
                                      OUTF, OUTF, 0);
    }
}

// round 5
// speedup vs baseline: 8.4445x; 1.3431x over previous
#include <cuda_runtime.h>
#include <math.h>
#include <stdint.h>

// Problem constants
#define Bn   512
#define Rr   5
#define Nn   64
#define Ff   172
#define Tt   100
#define Ee   272     // F + T
#define Kk   444     // F + EF + T
#define Dhh  136     // E / H
#define OUTF 172
#define CATN 1532    // R*E + F
#define HALF 32      // neighbor rows per split CTA

// ---------------- inter-kernel scratch ----------------
__device__ float g_X[Bn * Ee];                    // concat(src_node, src_time)
__device__ float g_q[Bn * Rr * Ee];               // q projections
__device__ float g_qk[Bn * Rr * 2 * Kk];          // (q_h · Wk_h) per head
__device__ float g_ctx[Bn * Rr * 2 * Kk];         // merged context per head
__device__ float g_attn[Bn * Rr * Ee];            // ctx · Wv^T + bv
__device__ float g_cat[Bn * CATN];                // [out | src_node]
__device__ float g_h1[Bn * OUTF];                 // fc1 output
__device__ float g_inv[Bn * Rr];                  // 1 => all neighbors padded
__device__ int   g_mask_u8;                       // mask dtype flag
// split-attention partials: [idx][half][h][...]
__device__ float g_pctx[Bn * Rr * 2 * 2 * Kk];    // partial contexts
__device__ float g_pml [Bn * Rr * 2 * 2 * 2];     // (m, l) per half per head
__device__ float g_pw  [Bn * Rr * 2 * 2 * HALF];  // unnormalized exp weights

__device__ __forceinline__ float warp_reduce(float v) {
    #pragma unroll
    for (int o = 16; o; o >>= 1) v += __shfl_down_sync(0xffffffffu, v, o);
    return v;
}
__device__ __forceinline__ float warp_max(float v) {
    #pragma unroll
    for (int o = 16; o; o >>= 1) v = fmaxf(v, __shfl_xor_sync(0xffffffffu, v, o));
    return v;
}
__device__ __forceinline__ float warp_sum_all(float v) {
    #pragma unroll
    for (int o = 16; o; o >>= 1) v += __shfl_xor_sync(0xffffffffu, v, o);
    return v;
}

// ==================== mask dtype detection ====================
__global__ void detect_mask_kernel(const unsigned int* __restrict__ m)
{
    const int nwords = 8192;
    unsigned int acc = 0;
    for (int i = threadIdx.x; i < nwords; i += blockDim.x) acc |= m[i];
    __shared__ unsigned int red[32];
    unsigned int v = acc;
    #pragma unroll
    for (int o = 16; o; o >>= 1) v |= __shfl_xor_sync(0xffffffffu, v, o);
    if ((threadIdx.x & 31) == 0) red[threadIdx.x >> 5] = v;
    __syncthreads();
    if (threadIdx.x == 0) {
        unsigned int t = 0;
        for (int w = 0; w < (int)(blockDim.x >> 5); ++w) t |= red[w];
        g_mask_u8 = (t > 1u) ? 1 : 0;
    }
}

// ==================== prep ====================
__global__ void prep_X_kernel(const float* __restrict__ src_node,
                              const float* __restrict__ src_time)
{
    const int b = blockIdx.x, tid = threadIdx.x;
    for (int e = tid; e < Ee; e += 256)
        g_X[b * Ee + e] = (e < Ff) ? src_node[b * Ff + e]
                                   : src_time[b * Tt + (e - Ff)];
    for (int j = tid; j < Ff; j += 256)
        g_cat[b * CATN + Rr * Ee + j] = src_node[b * Ff + j];
}

// ==================== generic batched tiled GEMM ====================
template<bool BT>
__global__ __launch_bounds__(256)
void gemm_kernel(const float* __restrict__ A, int lda, long strideAz,
                 const float* __restrict__ B, int ldb, long strideBz,
                 float* __restrict__ C, int ldc, long strideCz,
                 const float* __restrict__ bias, long strideBiasZ,
                 const float* __restrict__ invf, long strideInvZ, int invRowStride,
                 int N, int K, int epi)
{
    __shared__ float As[16][68];
    __shared__ float Bs[16][68];
    const int z = blockIdx.z;
    A += (size_t)z * strideAz;
    B += (size_t)z * strideBz;
    C += (size_t)z * strideCz;
    const float* bz = bias ? bias + (size_t)z * strideBiasZ : nullptr;
    const int m0 = blockIdx.x * 64, n0 = blockIdx.y * 64;
    const int tid = threadIdx.x;
    const int tn = tid & 15, tm = tid >> 4;

    float acc[4][4];
    #pragma unroll
    for (int i = 0; i < 4; ++i)
        #pragma unroll
        for (int j = 0; j < 4; ++j) acc[i][j] = 0.f;

    for (int k0 = 0; k0 < K; k0 += 16) {
        {
            const int kt = tid & 15, mt0 = tid >> 4;
            #pragma unroll
            for (int i = 0; i < 4; ++i) {
                const int mt = mt0 + i * 16;
                const int k = k0 + kt;
                As[kt][mt] = (k < K) ? A[(size_t)(m0 + mt) * lda + k] : 0.f;
            }
        }
        if (BT) {
            const int kt = tid & 15, nt0 = tid >> 4;
            #pragma unroll
            for (int i = 0; i < 4; ++i) {
                const int nt = nt0 + i * 16;
                const int k = k0 + kt, n = n0 + nt;
                Bs[kt][nt] = (k < K && n < N) ? B[(size_t)n * ldb + k] : 0.f;
            }
        } else {
            const int nt = tid & 63, kt0 = tid >> 6;
            #pragma unroll
            for (int i = 0; i < 4; ++i) {
                const int kt = kt0 + i * 4;
                const int k = k0 + kt, n = n0 + nt;
                Bs[kt][nt] = (k < K && n < N) ? B[(size_t)k * ldb + n] : 0.f;
            }
        }
        __syncthreads();
        #pragma unroll
        for (int kt = 0; kt < 16; ++kt) {
            const float4 a4 = *(const float4*)&As[kt][tm * 4];
            const float4 b4 = *(const float4*)&Bs[kt][tn * 4];
            const float av[4] = {a4.x, a4.y, a4.z, a4.w};
            const float bw[4] = {b4.x, b4.y, b4.z, b4.w};
            #pragma unroll
            for (int i = 0; i < 4; ++i)
                #pragma unroll
                for (int j = 0; j < 4; ++j)
                    acc[i][j] += av[i] * bw[j];
        }
        __syncthreads();
    }

    #pragma unroll
    for (int i = 0; i < 4; ++i) {
        const int row = m0 + tm * 4 + i;
        float vmul = 1.f;
        if (epi == 2 && invf) {
            const float fl = invf[(size_t)z * strideInvZ + (size_t)row * invRowStride];
            vmul = (fl > 0.5f) ? 0.f : 1.f;
        }
        #pragma unroll
        for (int j = 0; j < 4; ++j) {
            const int col = n0 + tn * 4 + j;
            if (col < N) {
                float v = acc[i][j] + (bz ? bz[col] : 0.f);
                if (epi == 1) v = fmaxf(v, 0.f);
                v *= vmul;
                C[(size_t)row * ldc + col] = v;
            }
        }
    }
}

// ==================== split attention ====================
// One CTA = 32 neighbor rows of one (b,r). smem-staged kin, local softmax,
// partial context. kin is read from DRAM exactly once across the whole pass.
#define KIN_LD 448                  // 444 padded to 448 (float4-aligned)
#define NSEG_F 43                   // 172 floats = 43 float4
#define NSEG_T 25                   // 100 floats = 25 float4
#define F4_A   (HALF * NSEG_F)      // 1376
#define F4_TOT (HALF * (2 * NSEG_F + NSEG_T))   // 3552

__global__ __launch_bounds__(256)
void split_attn_kernel(const float* __restrict__ neigh_feat,
                       const float* __restrict__ neigh_time,
                       const float* __restrict__ edge_feat,
                       const void* __restrict__ mask_raw)
{
    extern __shared__ float sm[];
    float* kin = sm;                          // HALF * 448
    float* qks = sm + HALF * KIN_LD;          // 2 * 448 (padded)
    float* ssm = qks + 2 * 448;               // 2 * 32 scores
    float* wsm = ssm + 64;                    // 2 * 32 exp weights
    float* msk = wsm + 64;                    // 32

    const int b = blockIdx.x, r = blockIdx.y, half = blockIdx.z;
    const int idx = b * Rr + r;
    const int n0 = half * HALF;
    const int tid = threadIdx.x;
    const int lane = tid & 31, warp = tid >> 5;

    // ---- mask rows for this half ----
    if (tid < HALF) {
        const int mi = (r * Bn + b) * Nn + n0 + tid;
        int mv;
        if (g_mask_u8) mv = ((const unsigned char*)mask_raw)[mi];
        else           mv = ((const int*)mask_raw)[mi];
        msk[tid] = (mv != 0) ? 1.f : 0.f;
    }

    // ---- qk vectors -> smem ([2][448], padded cols zero) ----
    for (int t = tid; t < 2 * 448; t += 256) {
        const int h = t / 448, c = t - h * 448;
        qks[t] = (c < Kk) ? g_qk[(size_t)idx * (2 * Kk) + h * Kk + c] : 0.f;
    }
    // zero kin pad columns [444,448)
    for (int t = tid; t < HALF * 4; t += 256) {
        const int row = t >> 2;
        kin[row * KIN_LD + Kk + (t & 3)] = 0.f;
    }

    // ---- load kin half-tile via float4 (high MLP) ----
    {
        const float4* pa = (const float4*)(neigh_feat + ((size_t)idx * Nn + n0) * Ff);
        const float4* pb = (const float4*)(edge_feat  + ((size_t)idx * Nn + n0) * Ff);
        const float4* pc = (const float4*)(neigh_time + ((size_t)idx * Nn + n0) * Tt);
        #pragma unroll
        for (int it = 0; it < 14; ++it) {
            const int t = tid + it * 256;
            if (t < F4_TOT) {
                float4 v;
                int row, col;
                if (t < F4_A) {
                    row = t / NSEG_F; col = (t - row * NSEG_F) * 4;
                    v = pa[row * NSEG_F + (t - row * NSEG_F)];
                } else if (t < 2 * F4_A) {
                    const int t2 = t - F4_A;
                    row = t2 / NSEG_F; col = Ff + (t2 - row * NSEG_F) * 4;
                    v = pb[row * NSEG_F + (t2 - row * NSEG_F)];
                } else {
                    const int t2 = t - 2 * F4_A;
                    row = t2 / NSEG_T; col = 2 * Ff + (t2 - row * NSEG_T) * 4;
                    v = pc[row * NSEG_T + (t2 - row * NSEG_T)];
                }
                *(float4*)&kin[row * KIN_LD + col] = v;
            }
        }
    }
    __syncthreads();

    // ---- scores: warp w handles rows w*4 .. w*4+3 ----
    {
        // register-cache qk coefficients for this lane
        float qk0[14], qk1[14];
        #pragma unroll
        for (int k = 0; k < 14; ++k) {
            qk0[k] = qks[lane + 32 * k];
            qk1[k] = qks[448 + lane + 32 * k];
        }
        const float scale = rsqrtf((float)Dhh);
        #pragma unroll
        for (int i = 0; i < 4; ++i) {
            const int nl = warp * 4 + i;
            const float* krow = &kin[nl * KIN_LD];
            float a0 = 0.f, a1 = 0.f;
            #pragma unroll
            for (int k = 0; k < 14; ++k) {
                const float v = krow[lane + 32 * k];
                a0 += qk0[k] * v;
                a1 += qk1[k] * v;
            }
            a0 = warp_reduce(a0);
            a1 = warp_reduce(a1);
            if (lane == 0) {
                const bool pad = msk[nl] > 0.5f;
                ssm[nl]      = pad ? -1e30f : a0 * scale;
                ssm[32 + nl] = pad ? -1e30f : a1 * scale;
            }
        }
    }
    __syncthreads();

    // ---- local masked softmax stats (warp 0) ----
    if (warp == 0) {
        #pragma unroll
        for (int h = 0; h < 2; ++h) {
            const float s = ssm[h * 32 + lane];
            const bool pad = msk[lane] > 0.5f;
            const float m = warp_max(s);
            const float e = pad ? 0.f : __expf(s - m);
            const float l = warp_sum_all(e);
            wsm[h * 32 + lane] = e;
            g_pw[((size_t)idx * 2 + half) * 64 + h * 32 + lane] = e;
            if (lane == 0) {
                g_pml[((size_t)idx * 2 + half) * 4 + h * 2 + 0] = m;
                g_pml[((size_t)idx * 2 + half) * 4 + h * 2 + 1] = l;
            }
        }
    }
    __syncthreads();

    // ---- partial ctx: ctx[h][c] = sum_n wexp[h][n] * kin[n][c] ----
    float* pout = &g_pctx[((size_t)idx * 2 + half) * (2 * Kk)];
    #pragma unroll
    for (int s = 0; s < 2; ++s) {
        const int c = tid + s * 256;
        if (c < Kk) {
            float a0 = 0.f, a1 = 0.f;
            #pragma unroll
            for (int n = 0; n < HALF; ++n) {
                const float v = kin[n * KIN_LD + c];
                a0 += wsm[n] * v;
                a1 += wsm[32 + n] * v;
            }
            pout[c]      = a0;
            pout[Kk + c] = a1;
        }
    }
}

// ==================== merge halves ====================
__global__ __launch_bounds__(128)
void merge_attn_kernel(float* __restrict__ wavg_out)
{
    const int idx = blockIdx.x;
    const int tid = threadIdx.x;

    __shared__ float f[2][2];     // [half][h] combine factors
    __shared__ int   inval;

    if (tid == 0) {
        float fac[2][2];
        bool invalid = false;
        #pragma unroll
        for (int h = 0; h < 2; ++h) {
            const float m0 = g_pml[((size_t)idx * 2 + 0) * 4 + h * 2 + 0];
            const float l0 = g_pml[((size_t)idx * 2 + 0) * 4 + h * 2 + 1];
            const float m1 = g_pml[((size_t)idx * 2 + 1) * 4 + h * 2 + 0];
            const float l1 = g_pml[((size_t)idx * 2 + 1) * 4 + h * 2 + 1];
            const float M = fmaxf(m0, m1);
            const float e0 = __expf(m0 - M), e1 = __expf(m1 - M);
            const float L = l0 * e0 + l1 * e1;
            if (L <= 0.f) { invalid = true; fac[0][h] = fac[1][h] = 0.f; }
            else { fac[0][h] = e0 / L; fac[1][h] = e1 / L; }
        }
        inval = invalid ? 1 : 0;
        g_inv[idx] = invalid ? 1.f : 0.f;
        f[0][0] = fac[0][0]; f[0][1] = fac[0][1];
        f[1][0] = fac[1][0]; f[1][1] = fac[1][1];
    }
    __syncthreads();

    const float* p0 = &g_pctx[((size_t)idx * 2 + 0) * (2 * Kk)];
    const float* p1 = &g_pctx[((size_t)idx * 2 + 1) * (2 * Kk)];
    float* out = &g_ctx[(size_t)idx * (2 * Kk)];

    if (inval) {
        for (int t = tid; t < 2 * Kk; t += 128) out[t] = 0.f;
        if (wavg_out && tid < Nn) wavg_out[idx * Nn + tid] = 0.f;
        return;
    }

    for (int t = tid; t < 2 * Kk; t += 128) {
        const int h = (t >= Kk) ? 1 : 0;
        out[t] = f[0][h] * p0[t] + f[1][h] * p1[t];
    }
    if (wavg_out && tid < Nn) {
        const int half = tid >> 5, nl = tid & 31;
        const float w0 = g_pw[((size_t)idx * 2 + half) * 64 + nl]      * f[half][0];
        const float w1 = g_pw[((size_t)idx * 2 + half) * 64 + 32 + nl] * f[half][1];
        wavg_out[idx * Nn + tid] = 0.5f * (w0 + w1);
    }
}

// ==================== launch ====================
extern "C" void kernel_launch(void* const* d_in, const int* in_sizes, int n_in,
                              void* d_out, int out_size)
{
    const float* src_node = (const float*)d_in[0];
    const float* src_time = (const float*)d_in[1];
    const float* nf       = (const float*)d_in[2];
    const float* nt       = (const float*)d_in[3];
    const float* ef       = (const float*)d_in[4];
    const void*  mask     = d_in[5];
    const float* Wq = (const float*)d_in[6];
    const float* Wk = (const float*)d_in[7];
    const float* Wv = (const float*)d_in[8];
    const float* bq = (const float*)d_in[9];
    // bk dropped: softmax-invariant
    const float* bv = (const float*)d_in[11];
    const float* Wo = (const float*)d_in[12];
    const float* bo = (const float*)d_in[13];
    const float* W1 = (const float*)d_in[14];
    const float* b1 = (const float*)d_in[15];
    const float* W2 = (const float*)d_in[16];
    const float* b2 = (const float*)d_in[17];

    float* merged = (float*)d_out;
    float* wavg = nullptr;
    if (out_size >= Bn * OUTF + Bn * Rr * Nn)
        wavg = merged + Bn * OUTF;

    float *pX, *pq, *pqk, *pctx, *pattn, *pcat, *ph1, *pinv;
    cudaGetSymbolAddress((void**)&pX,    g_X);
    cudaGetSymbolAddress((void**)&pq,    g_q);
    cudaGetSymbolAddress((void**)&pqk,   g_qk);
    cudaGetSymbolAddress((void**)&pctx,  g_ctx);
    cudaGetSymbolAddress((void**)&pattn, g_attn);
    cudaGetSymbolAddress((void**)&pcat,  g_cat);
    cudaGetSymbolAddress((void**)&ph1,   g_h1);
    cudaGetSymbolAddress((void**)&pinv,  g_inv);

    const int split_smem = (HALF * KIN_LD + 2 * 448 + 64 + 64 + 32 + 16) * (int)sizeof(float);
    cudaFuncSetAttribute(split_attn_kernel,
                         cudaFuncAttributeMaxDynamicSharedMemorySize, split_smem);

    detect_mask_kernel<<<1, 1024>>>((const unsigned int*)mask);
    prep_X_kernel<<<Bn, 256>>>(src_node, src_time);

    // q = X @ Wq[r]^T + bq
    {
        dim3 g(Bn / 64, (Ee + 63) / 64, Rr);
        gemm_kernel<true><<<g, 256>>>(pX, Ee, 0,
                                      Wq, Ee, (long)Ee * Ee,
                                      pq, Rr * Ee, Ee,
                                      bq, Ee,
                                      nullptr, 0, 0,
                                      Ee, Ee, 0);
    }
    // qk = q_h @ Wk_h
    {
        dim3 g(Bn / 64, (Kk + 63) / 64, Rr * 2);
        gemm_kernel<false><<<g, 256>>>(pq, Rr * Ee, Dhh,
                                       Wk, Kk, (long)Dhh * Kk,
                                       pqk, Rr * 2 * Kk, Kk,
                                       nullptr, 0,
                                       nullptr, 0, 0,
                                       Kk, Dhh, 0);
    }
    // split attention (one DRAM pass) + merge
    {
        dim3 g(Bn, Rr, 2);
        split_attn_kernel<<<g, 256, split_smem>>>(nf, nt, ef, mask);
        merge_attn_kernel<<<Bn * Rr, 128>>>(wavg);
    }
    // attn = ctx @ Wv_h^T + bv
    {
        dim3 g(Bn / 64, (Dhh + 63) / 64, Rr * 2);
        gemm_kernel<true><<<g, 256>>>(pctx, Rr * 2 * Kk, Kk,
                                      Wv, Kk, (long)Dhh * Kk,
                                      pattn, Rr * Ee, Dhh,
                                      bv, Dhh,
                                      nullptr, 0, 0,
                                      Dhh, Kk, 0);
    }
    // out = attn @ Wo[r]^T + bo, zero where invalid -> g_cat
    {
        dim3 g(Bn / 64, (Ee + 63) / 64, Rr);
        gemm_kernel<true><<<g, 256>>>(pattn, Rr * Ee, Ee,
                                      Wo, Ee, (long)Ee * Ee,
                                      pcat, CATN, Ee,
                                      bo, Ee,
                                      pinv, 1, Rr,
                                      Ee, Ee, 2);
    }
    // fc1
    {
        dim3 g(Bn / 64, (OUTF + 63) / 64, 1);
        gemm_kernel<true><<<g, 256>>>(pcat, CATN, 0,
                                      W1, CATN, 0,
                                      ph1, OUTF, 0,
                                      b1, 0,
                                      nullptr, 0, 0,
                                      OUTF, CATN, 1);
    }
    // fc2
    {
        dim3 g(Bn / 64, (OUTF + 63) / 64, 1);
        gemm_kernel<true><<<g, 256>>>(ph1, OUTF, 0,
                                      W2, OUTF, 0,
                                      merged, OUTF, 0,
                                      b2, 0,
                                      nullptr, 0, 0,
                                      OUTF, OUTF, 0);
    }
}